// round 1
// baseline (speedup 1.0000x reference)
#include <cuda_runtime.h>
#include <cstdint>

#define BATCH 4
#define CIN   64
#define COUT  64
#define WDIM  512
#define RES   32
#define TAPS  27

// Conv tiling
#define TCO  32          // couts per block (2 cout tiles)
#define TY   4
#define TZ   4
#define HX   34
#define HXP  36          // padded row
#define HY   6
#define HZ   6
#define CCH  4           // cin chunk
#define NCH  (CIN/CCH)

__device__ float g_styles[BATCH * CIN];
__device__ float g_wmod[BATCH * CIN * TAPS * COUT];   // [b][cin][tap][cout]

using u64 = unsigned long long;

__device__ __forceinline__ u64 fma2(u64 a, u64 b, u64 c) {
    u64 d;
    asm("fma.rn.f32x2 %0, %1, %2, %3;" : "=l"(d) : "l"(a), "l"(b), "l"(c));
    return d;
}
__device__ __forceinline__ u64 pack2(float lo, float hi) {
    u64 r;
    asm("mov.b64 %0, {%1, %2};" : "=l"(r) : "f"(lo), "f"(hi));
    return r;
}
__device__ __forceinline__ void un2(u64 v, float& lo, float& hi) {
    asm("mov.b64 {%0, %1}, %2;" : "=f"(lo), "=f"(hi) : "l"(v));
}

// ---------------------------------------------------------------------------
// Kernel A: styles[b][cin] = w_latent[b] . (affine_w[cin] / sqrt(512)) + affine_b[cin]
// ---------------------------------------------------------------------------
__global__ void k_styles(const float* __restrict__ wl,
                         const float* __restrict__ aw,
                         const float* __restrict__ ab) {
    __shared__ float s_wl[BATCH * WDIM];
    const int tid = threadIdx.x;                 // 256 threads
    for (int i = tid; i < BATCH * WDIM; i += 256) s_wl[i] = wl[i];
    __syncthreads();
    const int b = tid >> 6, c = tid & 63;
    const float* a = aw + c * WDIM;
    const float* w = s_wl + b * WDIM;
    float acc = 0.f;
#pragma unroll 8
    for (int j = 0; j < WDIM; j++) acc += w[j] * a[j];
    g_styles[tid] = acc * 0.044194173824159216f + ab[c];
}

// ---------------------------------------------------------------------------
// Kernel B: modulate + demodulate; store w as [b][cin][tap][cout]
// ---------------------------------------------------------------------------
__global__ void k_wmod(const float* __restrict__ weight) {
    const int b  = blockIdx.x >> 6;
    const int co = blockIdx.x & 63;
    const int tid = threadIdx.x;                 // 256
    __shared__ float s_sty[CIN];
    __shared__ float s_red[8];
    if (tid < CIN) s_sty[tid] = g_styles[b * CIN + tid];
    __syncthreads();
    const float* wr = weight + co * (CIN * TAPS);
    float s = 0.f;
    for (int i = tid; i < CIN * TAPS; i += 256) {
        float v = wr[i] * s_sty[i / TAPS];
        s += v * v;
    }
#pragma unroll
    for (int o = 16; o; o >>= 1) s += __shfl_xor_sync(0xffffffffu, s, o);
    if ((tid & 31) == 0) s_red[tid >> 5] = s;
    __syncthreads();
    if (tid < 32) {
        float t = (tid < 8) ? s_red[tid] : 0.f;
#pragma unroll
        for (int o = 4; o; o >>= 1) t += __shfl_xor_sync(0xffffffffu, t, o);
        if (tid == 0) s_red[0] = t;
    }
    __syncthreads();
    const float d = rsqrtf(s_red[0] + 1e-8f);
    for (int i = tid; i < CIN * TAPS; i += 256) {
        const int cin = i / TAPS;
        const int t   = i - cin * TAPS;
        g_wmod[((b * CIN + cin) * TAPS + t) * COUT + co] = wr[i] * s_sty[cin] * d;
    }
}

// ---------------------------------------------------------------------------
// Kernel C: direct conv3d (per-sample weights), noise add, bias, lrelu * sqrt(2)
// Block: 32 couts x (32 x TY x TZ) voxels. Thread: 8 couts x 8 voxels (f32x2 pairs).
// ---------------------------------------------------------------------------
__global__ void __launch_bounds__(256, 2)
k_conv(const float* __restrict__ x,
       const float* __restrict__ noise,
       const float* __restrict__ bias,
       float* __restrict__ out) {
    __shared__ float  s_in[CCH][HZ][HY][HXP];          // 20736 B
    __shared__ float2 s_w[CCH][TAPS][TCO];             // 27648 B (pre-duplicated pairs)

    const int tid = threadIdx.x;
    const int y0  = blockIdx.x * TY;
    const int z0  = blockIdx.y * TZ;
    const int b   = blockIdx.z >> 1;
    const int ct  = blockIdx.z & 1;

    const int cg  = tid >> 6;           // cout subgroup 0..3
    const int vg  = tid & 63;           // voxel group
    const int vx  = (vg & 3) * 8;
    const int vyL = (vg >> 2) & 3;
    const int vzL = vg >> 4;

    u64 acc[8][4];
#pragma unroll
    for (int j = 0; j < 8; j++)
#pragma unroll
        for (int p = 0; p < 4; p++) acc[j][p] = 0ull;

    for (int ch = 0; ch < NCH; ch++) {
        const int cb = ch * CCH;
        __syncthreads();   // previous chunk fully consumed before overwrite

        // --- stage input halo tile: CCH x 6 x 6 x 34 ---
        for (int i = tid; i < CCH * HZ * HY * HX; i += 256) {
            int c  = i / (HZ * HY * HX);
            int r2 = i - c * (HZ * HY * HX);
            int hz = r2 / (HY * HX);
            int r3 = r2 - hz * (HY * HX);
            int hy = r3 / HX;
            int hx = r3 - hy * HX;
            int gz = z0 - 1 + hz, gy = y0 - 1 + hy, gx = hx - 1;
            float v = 0.f;
            if ((unsigned)gz < RES && (unsigned)gy < RES && (unsigned)gx < RES)
                v = x[((b * CIN + cb + c) * (RES * RES * RES)) + gz * (RES * RES) + gy * RES + gx];
            s_in[c][hz][hy][hx] = v;
        }
        // --- stage weights (duplicated into float2) ---
        for (int i = tid; i < CCH * TAPS * TCO; i += 256) {
            int c  = i / (TAPS * TCO);
            int r2 = i - c * (TAPS * TCO);
            int t  = r2 >> 5;
            int co = r2 & 31;
            float w = g_wmod[((b * CIN + cb + c) * TAPS + t) * COUT + ct * TCO + co];
            s_w[c][t][co] = make_float2(w, w);
        }
        __syncthreads();

        // --- compute ---
#pragma unroll 1
        for (int c = 0; c < CCH; c++) {
#pragma unroll 1
            for (int dz = 0; dz < 3; dz++) {
#pragma unroll
                for (int dy = 0; dy < 3; dy++) {
                    const float* row = &s_in[c][vzL + dz][vyL + dy][vx];
                    u64 p0 = *(const u64*)(row + 0);
                    u64 p1 = *(const u64*)(row + 2);
                    u64 p2 = *(const u64*)(row + 4);
                    u64 p3 = *(const u64*)(row + 6);
                    u64 p4 = *(const u64*)(row + 8);
                    float e0, e1, e2, e3, e4, e5, e6, e7, e8, e9;
                    un2(p0, e0, e1); un2(p1, e2, e3); un2(p2, e4, e5);
                    un2(p3, e6, e7); un2(p4, e8, e9);
                    const u64 q0 = pack2(e1, e2);
                    const u64 q1 = pack2(e3, e4);
                    const u64 q2 = pack2(e5, e6);
                    const u64 q3 = pack2(e7, e8);
#pragma unroll
                    for (int dx = 0; dx < 3; dx++) {
                        u64 i0, i1, i2, i3;
                        if (dx == 0)      { i0 = p0; i1 = p1; i2 = p2; i3 = p3; }
                        else if (dx == 1) { i0 = q0; i1 = q1; i2 = q2; i3 = q3; }
                        else              { i0 = p1; i1 = p2; i2 = p3; i3 = p4; }
                        const u64* wrow = (const u64*)&s_w[c][dz * 9 + dy * 3 + dx][cg * 8];
#pragma unroll
                        for (int j = 0; j < 8; j++) {
                            const u64 w2 = wrow[j];
                            acc[j][0] = fma2(w2, i0, acc[j][0]);
                            acc[j][1] = fma2(w2, i1, acc[j][1]);
                            acc[j][2] = fma2(w2, i2, acc[j][2]);
                            acc[j][3] = fma2(w2, i3, acc[j][3]);
                        }
                    }
                }
            }
        }
    }

    // --- epilogue: + noise + bias, lrelu(0.2) * sqrt(2) ---
    const int vz = z0 + vzL, vy = y0 + vyL;
    const int vbase = vz * (RES * RES) + vy * RES + vx;
    float nz[8];
    const float* np = noise + b * (RES * RES * RES) + vbase;
#pragma unroll
    for (int k = 0; k < 8; k++) nz[k] = np[k];
    const float gain = 1.4142135623730951f;
    const int co0 = ct * TCO + cg * 8;
#pragma unroll
    for (int j = 0; j < 8; j++) {
        const int co = co0 + j;
        const float bb = bias[co];
        float o[8];
#pragma unroll
        for (int p = 0; p < 4; p++) un2(acc[j][p], o[2 * p], o[2 * p + 1]);
        float4 r0, r1;
        float v[8];
#pragma unroll
        for (int k = 0; k < 8; k++) {
            float t = o[k] + nz[k] + bb;
            v[k] = (t > 0.f ? t : 0.2f * t) * gain;
        }
        r0 = make_float4(v[0], v[1], v[2], v[3]);
        r1 = make_float4(v[4], v[5], v[6], v[7]);
        float* op = out + (size_t)(b * COUT + co) * (RES * RES * RES) + vbase;
        *(float4*)(op)     = r0;
        *(float4*)(op + 4) = r1;
    }
}

// ---------------------------------------------------------------------------
extern "C" void kernel_launch(void* const* d_in, const int* in_sizes, int n_in,
                              void* d_out, int out_size) {
    const float* x      = (const float*)d_in[0];
    const float* wl     = (const float*)d_in[1];
    const float* weight = (const float*)d_in[2];
    const float* aw     = (const float*)d_in[3];
    const float* ab     = (const float*)d_in[4];
    const float* noise  = (const float*)d_in[5];
    const float* bias   = (const float*)d_in[6];
    float* out = (float*)d_out;

    k_styles<<<1, 256>>>(wl, aw, ab);
    k_wmod<<<BATCH * COUT, 256>>>(weight);
    dim3 grid(RES / TY, RES / TZ, BATCH * (COUT / TCO));   // (8, 8, 8)
    k_conv<<<grid, 256>>>(x, noise, bias, out);
}